// round 4
// baseline (speedup 1.0000x reference)
#include <cuda_runtime.h>
#include <cuda_bf16.h>
#include <cstdint>
#include <cfloat>

#define N_Q     2048
#define M_ROWS  100000
#define DIMS    128
#define KNN     5

#define NSLICES   9
#define TILE_R    128
#define NTILES    87
#define SLICE_LEN (NTILES * TILE_R)   // 11136; 9*11136 >= 100000
#define QT        128                  // queries per CTA
#define TPB       384                  // 8 GEMM warps + 4 scan warps

#define TPQ       16                   // candidates kept per (query, slice)
#define RSEL      16                   // exact-refined candidates per query

// ---- device scratch ----
__device__ __nv_bfloat16 g_hiF2[N_Q * DIMS];     // bf16(-2*F)
__device__ __nv_bfloat16 g_hiB [M_ROWS * DIMS];  // bf16(B)
__device__ float g_y2[M_ROWS];
__device__ float g_cand_val[NSLICES][N_Q][TPQ];
__device__ int   g_cand_idx[NSLICES][N_Q][TPQ];

// ---- smem layout (bytes) ----
#define AB_STRIDE 272                  // A/B row stride: conflict-free LDSM
#define SM_A    0                      // 128 * 272 = 34816
#define SM_B0   34816
#define SM_B1   69632
#define SM_D0   104448                 // bf16 D, 128 rows * 256B = 32768
#define SM_D1   137216
#define SM_Y2   169984                 // float[2][128]
#define SMEM_TOTAL 171072

// ---------------------------------------------------------------------------
__device__ __forceinline__ uint32_t s2u(const void* p) {
    uint32_t a;
    asm("{ .reg .u64 t; cvta.to.shared.u64 t, %1; cvt.u32.u64 %0, t; }" : "=r"(a) : "l"(p));
    return a;
}
__device__ __forceinline__ void cp16(uint32_t dst, const void* src) {
    asm volatile("cp.async.cg.shared.global [%0], [%1], 16;" :: "r"(dst), "l"(src) : "memory");
}
__device__ __forceinline__ void ldsm_x4(uint32_t& r0, uint32_t& r1, uint32_t& r2, uint32_t& r3,
                                        uint32_t addr) {
    asm volatile("ldmatrix.sync.aligned.m8n8.x4.shared.b16 {%0,%1,%2,%3}, [%4];"
                 : "=r"(r0), "=r"(r1), "=r"(r2), "=r"(r3) : "r"(addr));
}
__device__ __forceinline__ void mma16816(float& d0, float& d1, float& d2, float& d3,
                                         uint32_t a0, uint32_t a1, uint32_t a2, uint32_t a3,
                                         uint32_t b0, uint32_t b1) {
    asm volatile("mma.sync.aligned.m16n8k16.row.col.f32.bf16.bf16.f32 "
                 "{%0,%1,%2,%3}, {%4,%5,%6,%7}, {%8,%9}, {%0,%1,%2,%3};"
                 : "+f"(d0), "+f"(d1), "+f"(d2), "+f"(d3)
                 : "r"(a0), "r"(a1), "r"(a2), "r"(a3), "r"(b0), "r"(b1));
}
__device__ __forceinline__ uint32_t pack_bf16x2(float lo, float hi) {
    uint32_t d;
    asm("cvt.rn.bf16x2.f32 %0, %1, %2;" : "=r"(d) : "f"(hi), "f"(lo));
    return d;
}

// ---------------------------------------------------------------------------
// Convert: bf16(B) rows, bf16(-2*F) rows, y2 norms. One warp per row.
__global__ void convert_kernel(const float* __restrict__ F, const float* __restrict__ B) {
    int gw   = (blockIdx.x * blockDim.x + threadIdx.x) >> 5;
    int lane = threadIdx.x & 31;
    if (gw >= N_Q + M_ROWS) return;
    bool isF = gw < N_Q;
    int row  = isF ? gw : gw - N_Q;
    const float* src = (isF ? F : B) + (size_t)row * DIMS;
    float4 v = reinterpret_cast<const float4*>(src)[lane];
    if (!isF) {
        float s = v.x*v.x + v.y*v.y + v.z*v.z + v.w*v.w;
        #pragma unroll
        for (int o = 16; o; o >>= 1) s += __shfl_xor_sync(0xffffffffu, s, o);
        if (lane == 0) g_y2[row] = s;
    }
    float sc = isF ? -2.0f : 1.0f;
    __nv_bfloat162 p0{__float2bfloat16_rn(sc * v.x), __float2bfloat16_rn(sc * v.y)};
    __nv_bfloat162 p1{__float2bfloat16_rn(sc * v.z), __float2bfloat16_rn(sc * v.w)};
    __nv_bfloat162* hp = reinterpret_cast<__nv_bfloat162*>(isF ? g_hiF2 : g_hiB);
    hp[(size_t)row * 64 + 2 * lane]     = p0;
    hp[(size_t)row * 64 + 2 * lane + 1] = p1;
}

// ---------------------------------------------------------------------------
// Main: warp-specialized. Warps 0-7: bf16 mma GEMM -> bf16 D.  Warps 8-11:
// scan D (1 thread = 1 query), maintain top-16 (val,idx) in registers.
__global__ void __launch_bounds__(TPB, 1)
knn_mma_kernel() {
    extern __shared__ char smem[];
    const uint32_t sb = s2u(smem);
    float* y2s = reinterpret_cast<float*>(smem + SM_Y2);

    const int tid  = threadIdx.x;
    const int wid  = tid >> 5;
    const int lane = tid & 31;
    const int qblock  = blockIdx.x * QT;
    const int slice   = blockIdx.y;
    const int row_beg = slice * SLICE_LEN;

    // Stage A (queries) once: 2048 16B chunks, all 384 threads.
    for (int idx = tid; idx < QT * 16; idx += TPB) {
        int r = idx >> 4, cc = idx & 15;
        uint4 v = *reinterpret_cast<const uint4*>(
            reinterpret_cast<const char*>(g_hiF2) + ((size_t)(qblock + r) * 256 + cc * 16));
        *reinterpret_cast<uint4*>(smem + SM_A + r * AB_STRIDE + cc * 16) = v;
    }
    // Prefetch B tile 0 into buffer 0 (GEMM threads only).
    if (tid < 256) {
        #pragma unroll
        for (int i = 0; i < 8; i++) {
            int chunk = tid + 256 * i;
            int r = chunk >> 4, cc = chunk & 15;
            int rg = row_beg + r;
            int rc = rg < M_ROWS ? rg : M_ROWS - 1;
            cp16(sb + SM_B0 + r * AB_STRIDE + cc * 16,
                 reinterpret_cast<const char*>(g_hiB) + ((size_t)rc * 256 + cc * 16));
        }
        if (tid < 128) {
            int rg = row_beg + tid;
            y2s[tid] = (rg < M_ROWS) ? g_y2[rg] : FLT_MAX;
        }
        asm volatile("cp.async.commit_group;" ::: "memory");
    }
    __syncthreads();

    if (wid < 8) {
        // =================== GEMM warps ===================
        const int wm = wid & 3;        // 4 m-chunks of 32 rows
        const int wn = wid >> 2;       // 2 n-chunks of 64 cols
        const uint32_t Abase = sb + SM_A + (wm * 32) * AB_STRIDE;
        const int arow = lane & 15;
        const int acol = (lane >> 4) * 16;
        const int brow = (lane & 7) + (lane >> 4) * 8;
        const int bcol = ((lane >> 3) & 1) * 16;

        for (int t = 0; t < NTILES; t++) {
            const int buf = t & 1;
            const uint32_t Bb = sb + (buf ? SM_B1 : SM_B0);

            asm volatile("bar.sync 1, 256;" ::: "memory");  // B[buf^1] readers done
            if (t + 1 < NTILES) {
                int tb = row_beg + (t + 1) * TILE_R;
                uint32_t Bn = sb + (buf ? SM_B0 : SM_B1);
                #pragma unroll
                for (int i = 0; i < 8; i++) {
                    int chunk = tid + 256 * i;
                    int r = chunk >> 4, cc = chunk & 15;
                    int rg = tb + r;
                    int rc = rg < M_ROWS ? rg : M_ROWS - 1;
                    cp16(Bn + r * AB_STRIDE + cc * 16,
                         reinterpret_cast<const char*>(g_hiB) + ((size_t)rc * 256 + cc * 16));
                }
                if (tid < 128) {
                    int rg = tb + tid;
                    y2s[(buf ^ 1) * 128 + tid] = (rg < M_ROWS) ? g_y2[rg] : FLT_MAX;
                }
                asm volatile("cp.async.commit_group;" ::: "memory");
                asm volatile("cp.async.wait_group 1;" ::: "memory");
            } else {
                asm volatile("cp.async.wait_group 0;" ::: "memory");
            }
            asm volatile("bar.sync 1, 256;" ::: "memory");  // B[buf] ready

            // ---- GEMM: warp tile 32(q) x 64(r), K=128
            float acc[2][8][4];
            #pragma unroll
            for (int mt = 0; mt < 2; mt++)
                #pragma unroll
                for (int nt = 0; nt < 8; nt++)
                    #pragma unroll
                    for (int e = 0; e < 4; e++) acc[mt][nt][e] = 0.f;

            const uint32_t Bbase = Bb + (wn * 64) * AB_STRIDE;
            #pragma unroll
            for (int ks = 0; ks < 8; ks++) {
                uint32_t a[2][4];
                #pragma unroll
                for (int mt = 0; mt < 2; mt++)
                    ldsm_x4(a[mt][0], a[mt][1], a[mt][2], a[mt][3],
                            Abase + (mt * 16 + arow) * AB_STRIDE + ks * 32 + acol);
                uint32_t b[8][2];
                #pragma unroll
                for (int nt2 = 0; nt2 < 4; nt2++) {
                    uint32_t r0, r1, r2, r3;
                    ldsm_x4(r0, r1, r2, r3,
                            Bbase + (nt2 * 16 + brow) * AB_STRIDE + ks * 32 + bcol);
                    b[nt2 * 2][0] = r0; b[nt2 * 2][1] = r1;
                    b[nt2 * 2 + 1][0] = r2; b[nt2 * 2 + 1][1] = r3;
                }
                #pragma unroll
                for (int mt = 0; mt < 2; mt++)
                    #pragma unroll
                    for (int nt = 0; nt < 8; nt++)
                        mma16816(acc[mt][nt][0], acc[mt][nt][1], acc[mt][nt][2], acc[mt][nt][3],
                                 a[mt][0], a[mt][1], a[mt][2], a[mt][3],
                                 b[nt][0], b[nt][1]);
            }

            // ---- STS D bf16 with granule rotation p = (g + row) & 15
            const float* y2t = y2s + buf * 128;
            const uint32_t Db = sb + (buf ? SM_D1 : SM_D0);
            #pragma unroll
            for (int mt = 0; mt < 2; mt++) {
                int row0 = wm * 32 + mt * 16 + (lane >> 2);
                #pragma unroll
                for (int nt = 0; nt < 8; nt++) {
                    int col = wn * 64 + nt * 8 + 2 * (lane & 3);
                    int g   = wn * 8 + nt;
                    float2 y2p = *reinterpret_cast<const float2*>(y2t + col);
                    uint32_t d0 = pack_bf16x2(acc[mt][nt][0] + y2p.x, acc[mt][nt][1] + y2p.y);
                    uint32_t d1 = pack_bf16x2(acc[mt][nt][2] + y2p.x, acc[mt][nt][3] + y2p.y);
                    uint32_t a0 = Db + row0 * 256 + (((g + row0) & 15) << 4) + (lane & 3) * 4;
                    uint32_t a1 = Db + (row0 + 8) * 256 + (((g + row0 + 8) & 15) << 4) + (lane & 3) * 4;
                    asm volatile("st.shared.b32 [%0], %1;" :: "r"(a0), "r"(d0) : "memory");
                    asm volatile("st.shared.b32 [%0], %1;" :: "r"(a1), "r"(d1) : "memory");
                }
            }
            asm volatile("bar.sync 2, 384;" ::: "memory");  // D[buf] handoff to scan
        }
    } else {
        // =================== scan warps: 1 thread = 1 query ===================
        const int q = tid - 256;                 // 0..127
        float tv[TPQ]; int tix[TPQ];
        #pragma unroll
        for (int k = 0; k < TPQ; k++) { tv[k] = FLT_MAX; tix[k] = -1; }

        for (int t = 0; t < NTILES; t++) {
            const int buf = t & 1;
            asm volatile("bar.sync 2, 384;" ::: "memory");  // D[buf] ready
            const uint32_t Db = sb + (buf ? SM_D1 : SM_D0) + q * 256;
            const int idx_base = row_beg + t * TILE_R;
            #pragma unroll
            for (int g = 0; g < 16; g++) {
                int p = (g + q) & 15;
                uint4 w;
                asm volatile("ld.shared.v4.b32 {%0,%1,%2,%3}, [%4];"
                             : "=r"(w.x), "=r"(w.y), "=r"(w.z), "=r"(w.w)
                             : "r"(Db + (p << 4)));
                uint32_t ww[4] = {w.x, w.y, w.z, w.w};
                #pragma unroll
                for (int h = 0; h < 4; h++) {
                    float2 f = __bfloat1622float2(
                        *reinterpret_cast<const __nv_bfloat162*>(&ww[h]));
                    float vv[2] = {f.x, f.y};
                    #pragma unroll
                    for (int e = 0; e < 2; e++) {
                        float val = vv[e];
                        if (val < tv[TPQ - 1]) {
                            tv[TPQ - 1] = val;
                            tix[TPQ - 1] = idx_base + g * 8 + 2 * h + e;
                            #pragma unroll
                            for (int k = TPQ - 1; k > 0; k--) {
                                if (tv[k] < tv[k - 1]) {
                                    float tf = tv[k - 1]; tv[k - 1] = tv[k]; tv[k] = tf;
                                    int   ti = tix[k - 1]; tix[k - 1] = tix[k]; tix[k] = ti;
                                }
                            }
                        }
                    }
                }
            }
        }
        #pragma unroll
        for (int k = 0; k < TPQ; k++) {
            g_cand_val[slice][qblock + q][k] = tv[k];
            g_cand_idx[slice][qblock + q][k] = tix[k];
        }
    }
}

// ---------------------------------------------------------------------------
// Refine: per query (one warp): approx-top-16 of 144 candidates -> exact fp32
// distances -> top-5 -> sqrt, normalize, mean.
__global__ void __launch_bounds__(256)
refine_kernel(const float* __restrict__ F, const float* __restrict__ B,
              const float* __restrict__ minv, const float* __restrict__ maxv,
              float* __restrict__ out) {
    __shared__ float sv[8][NSLICES * TPQ];
    __shared__ int   si[8][NSLICES * TPQ];
    __shared__ int   sel[8][RSEL];
    __shared__ float ex[8][RSEL];

    const int w    = threadIdx.x >> 5;
    const int lane = threadIdx.x & 31;
    const int q    = blockIdx.x * 8 + w;
    const int NC   = NSLICES * TPQ;   // 144

    for (int i = lane; i < NC; i += 32) {
        sv[w][i] = g_cand_val[i / TPQ][q][i % TPQ];
        si[w][i] = g_cand_idx[i / TPQ][q][i % TPQ];
    }
    __syncwarp();

    float4 xv = reinterpret_cast<const float4*>(F + (size_t)q * DIMS)[lane];
    float x2 = xv.x*xv.x + xv.y*xv.y + xv.z*xv.z + xv.w*xv.w;
    #pragma unroll
    for (int o = 16; o; o >>= 1) x2 += __shfl_xor_sync(0xffffffffu, x2, o);

    for (int i = lane; i < NC; i += 32) {
        float v = sv[w][i];
        int r = 0;
        for (int j = 0; j < NC; j++) {
            float u = sv[w][j];
            r += (u < v) || (u == v && j < i);
        }
        if (r < RSEL) sel[w][r] = si[w][i];
    }
    __syncwarp();

    for (int c = 0; c < RSEL; c++) {
        int id = sel[w][c];
        float d2 = FLT_MAX;
        if (id >= 0) {
            float4 yv = reinterpret_cast<const float4*>(B + (size_t)id * DIMS)[lane];
            float p = yv.x*yv.x + yv.y*yv.y + yv.z*yv.z + yv.w*yv.w
                    - 2.0f * (xv.x*yv.x + xv.y*yv.y + xv.z*yv.z + xv.w*yv.w);
            #pragma unroll
            for (int o = 16; o; o >>= 1) p += __shfl_xor_sync(0xffffffffu, p, o);
            d2 = x2 + p;
        }
        if (lane == 0) ex[w][c] = d2;
    }
    __syncwarp();

    if (lane == 0) {
        float best[KNN];
        #pragma unroll
        for (int k = 0; k < KNN; k++) best[k] = FLT_MAX;
        #pragma unroll
        for (int c = 0; c < RSEL; c++) {
            float v = ex[w][c];
            if (v < best[KNN - 1]) {
                best[KNN - 1] = v;
                #pragma unroll
                for (int k = KNN - 1; k > 0; k--) {
                    if (best[k] < best[k - 1]) {
                        float tf = best[k - 1]; best[k - 1] = best[k]; best[k] = tf;
                    }
                }
            }
        }
        float mn = *minv, mx = *maxv;
        float inv = 1.f / (mx - mn);
        float sum = 0.f;
        #pragma unroll
        for (int k = 0; k < KNN; k++)
            sum += (sqrtf(fmaxf(best[k], 0.f)) - mn) * inv;
        out[q] = sum * (1.0f / KNN);
    }
}

// ---------------------------------------------------------------------------
extern "C" void kernel_launch(void* const* d_in, const int* in_sizes, int n_in,
                              void* d_out, int out_size) {
    const float* F    = (const float*)d_in[0];
    const float* B    = (const float*)d_in[1];
    const float* minv = (const float*)d_in[2];
    const float* maxv = (const float*)d_in[3];
    float* out = (float*)d_out;

    static bool attr_done = false;
    if (!attr_done) {
        cudaFuncSetAttribute(knn_mma_kernel,
                             cudaFuncAttributeMaxDynamicSharedMemorySize, SMEM_TOTAL);
        attr_done = true;
    }

    int conv_blocks = ((N_Q + M_ROWS) * 32 + 255) / 256;
    convert_kernel<<<conv_blocks, 256>>>(F, B);

    dim3 grid(N_Q / QT, NSLICES);
    knn_mma_kernel<<<grid, TPB, SMEM_TOTAL>>>();

    refine_kernel<<<N_Q / 8, 256>>>(F, B, minv, maxv, out);
}

// round 5
// speedup vs baseline: 2.9064x; 2.9064x over previous
#include <cuda_runtime.h>
#include <cuda_bf16.h>
#include <cstdint>
#include <cfloat>

#define N_Q     2048
#define M_ROWS  100000
#define DIMS    128
#define KNN     5

#define NSLICES   9
#define TILE_R    128
#define NTILES    87
#define SLICE_LEN (NTILES * TILE_R)   // 11136; 9*11136 >= 100000
#define QT        128                  // queries per CTA
#define TPB       256                  // 8 warps

#define TPQ       16                   // candidates kept per (query, slice)
#define RSEL      16                   // exact-refined candidates per query

// ---- device scratch ----
__device__ __nv_bfloat16 g_hiF2[N_Q * DIMS];     // bf16(-2*F)
__device__ __nv_bfloat16 g_hiB [M_ROWS * DIMS];  // bf16(B)
__device__ float g_y2[M_ROWS];
__device__ float g_cand_val[NSLICES][N_Q][TPQ];
__device__ int   g_cand_idx[NSLICES][N_Q][TPQ];

// ---- smem layout (bytes) ----
#define AB_STRIDE 272                  // A/B row stride: conflict-free LDSM
#define SM_A    0                      // 128*272 = 34816
#define SM_B0   34816
#define SM_B1   69632
#define SM_D    104448                 // bf16 D: 128 rows * 260B = 33280
#define D_STRIDE_B 260                 // 65 words (odd) -> conflict-free scan
#define SM_Y2   137728                 // float[2][128]
#define SMEM_TOTAL 138752

// ---------------------------------------------------------------------------
__device__ __forceinline__ uint32_t s2u(const void* p) {
    uint32_t a;
    asm("{ .reg .u64 t; cvta.to.shared.u64 t, %1; cvt.u32.u64 %0, t; }" : "=r"(a) : "l"(p));
    return a;
}
__device__ __forceinline__ void cp16(uint32_t dst, const void* src) {
    asm volatile("cp.async.cg.shared.global [%0], [%1], 16;" :: "r"(dst), "l"(src) : "memory");
}
__device__ __forceinline__ void ldsm_x4(uint32_t& r0, uint32_t& r1, uint32_t& r2, uint32_t& r3,
                                        uint32_t addr) {
    asm volatile("ldmatrix.sync.aligned.m8n8.x4.shared.b16 {%0,%1,%2,%3}, [%4];"
                 : "=r"(r0), "=r"(r1), "=r"(r2), "=r"(r3) : "r"(addr));
}
__device__ __forceinline__ void mma16816(float& d0, float& d1, float& d2, float& d3,
                                         uint32_t a0, uint32_t a1, uint32_t a2, uint32_t a3,
                                         uint32_t b0, uint32_t b1) {
    asm volatile("mma.sync.aligned.m16n8k16.row.col.f32.bf16.bf16.f32 "
                 "{%0,%1,%2,%3}, {%4,%5,%6,%7}, {%8,%9}, {%0,%1,%2,%3};"
                 : "+f"(d0), "+f"(d1), "+f"(d2), "+f"(d3)
                 : "r"(a0), "r"(a1), "r"(a2), "r"(a3), "r"(b0), "r"(b1));
}
__device__ __forceinline__ uint32_t pack_bf16x2(float lo, float hi) {
    uint32_t d;
    asm("cvt.rn.bf16x2.f32 %0, %1, %2;" : "=r"(d) : "f"(hi), "f"(lo));
    return d;
}

// ---------------------------------------------------------------------------
// Convert: bf16(B) rows, bf16(-2*F) rows, y2 norms. One warp per row.
__global__ void convert_kernel(const float* __restrict__ F, const float* __restrict__ B) {
    int gw   = (blockIdx.x * blockDim.x + threadIdx.x) >> 5;
    int lane = threadIdx.x & 31;
    if (gw >= N_Q + M_ROWS) return;
    bool isF = gw < N_Q;
    int row  = isF ? gw : gw - N_Q;
    const float* src = (isF ? F : B) + (size_t)row * DIMS;
    float4 v = reinterpret_cast<const float4*>(src)[lane];
    if (!isF) {
        float s = v.x*v.x + v.y*v.y + v.z*v.z + v.w*v.w;
        #pragma unroll
        for (int o = 16; o; o >>= 1) s += __shfl_xor_sync(0xffffffffu, s, o);
        if (lane == 0) g_y2[row] = s;
    }
    float sc = isF ? -2.0f : 1.0f;
    __nv_bfloat162 p0{__float2bfloat16_rn(sc * v.x), __float2bfloat16_rn(sc * v.y)};
    __nv_bfloat162 p1{__float2bfloat16_rn(sc * v.z), __float2bfloat16_rn(sc * v.w)};
    __nv_bfloat162* hp = reinterpret_cast<__nv_bfloat162*>(isF ? g_hiF2 : g_hiB);
    hp[(size_t)row * 64 + 2 * lane]     = p0;
    hp[(size_t)row * 64 + 2 * lane + 1] = p1;
}

// ---------------------------------------------------------------------------
// Main: mma.sync GEMM (A-frags register-resident) + bf16 D + gated scan.
__global__ void __launch_bounds__(TPB, 1)
knn_mma_kernel() {
    extern __shared__ char smem[];
    const uint32_t sb = s2u(smem);
    float* y2s = reinterpret_cast<float*>(smem + SM_Y2);

    const int tid  = threadIdx.x;
    const int wid  = tid >> 5;
    const int lane = tid & 31;
    const int wm   = wid & 3;        // 4 m-chunks of 32 rows
    const int wn   = wid >> 2;       // 2 n-chunks of 64 cols
    const int qblock  = blockIdx.x * QT;
    const int slice   = blockIdx.y;
    const int row_beg = slice * SLICE_LEN;

    // Stage A (queries): 2048 16B chunks, 8 per thread.
    #pragma unroll
    for (int i = 0; i < 8; i++) {
        int chunk = tid + TPB * i;
        int r = chunk >> 4, cc = chunk & 15;
        uint4 v = *reinterpret_cast<const uint4*>(
            reinterpret_cast<const char*>(g_hiF2) + ((size_t)(qblock + r) * 256 + cc * 16));
        *reinterpret_cast<uint4*>(smem + SM_A + r * AB_STRIDE + cc * 16) = v;
    }
    // Prefetch B tile 0 into buffer 0.
    {
        #pragma unroll
        for (int i = 0; i < 8; i++) {
            int chunk = tid + TPB * i;
            int r = chunk >> 4, cc = chunk & 15;
            int rg = row_beg + r;
            int rc = rg < M_ROWS ? rg : M_ROWS - 1;
            cp16(sb + SM_B0 + r * AB_STRIDE + cc * 16,
                 reinterpret_cast<const char*>(g_hiB) + ((size_t)rc * 256 + cc * 16));
        }
        if (tid < 128) {
            int rg = row_beg + tid;
            y2s[tid] = (rg < M_ROWS) ? g_y2[rg] : FLT_MAX;
        }
        asm volatile("cp.async.commit_group;" ::: "memory");
    }
    __syncthreads();

    // Hoist A fragments into registers (loop-invariant across all 87 tiles).
    const int arow = lane & 15;
    const int acol = (lane >> 4) * 16;
    const int brow = (lane & 7) + (lane >> 4) * 8;
    const int bcol = ((lane >> 3) & 1) * 16;
    const uint32_t Abase = sb + SM_A + (wm * 32) * AB_STRIDE;
    uint32_t afr[8][2][4];
    #pragma unroll
    for (int ks = 0; ks < 8; ks++)
        #pragma unroll
        for (int mt = 0; mt < 2; mt++)
            ldsm_x4(afr[ks][mt][0], afr[ks][mt][1], afr[ks][mt][2], afr[ks][mt][3],
                    Abase + (mt * 16 + arow) * AB_STRIDE + ks * 32 + acol);

    // Scan state: thread owns (query sq, half sh). Top-8 (val,idx), ascending.
    const int sq = tid & 127;
    const int sh = tid >> 7;
    float tv[8]; int tix[8];
    #pragma unroll
    for (int k = 0; k < 8; k++) { tv[k] = FLT_MAX; tix[k] = -1; }

    for (int t = 0; t < NTILES; t++) {
        const int buf = t & 1;
        const uint32_t Bb = sb + (buf ? SM_B1 : SM_B0);

        __syncthreads();   // prev scan done; B[buf^1] consumed

        if (t + 1 < NTILES) {
            int tb = row_beg + (t + 1) * TILE_R;
            uint32_t Bn = sb + (buf ? SM_B0 : SM_B1);
            #pragma unroll
            for (int i = 0; i < 8; i++) {
                int chunk = tid + TPB * i;
                int r = chunk >> 4, cc = chunk & 15;
                int rg = tb + r;
                int rc = rg < M_ROWS ? rg : M_ROWS - 1;
                cp16(Bn + r * AB_STRIDE + cc * 16,
                     reinterpret_cast<const char*>(g_hiB) + ((size_t)rc * 256 + cc * 16));
            }
            if (tid < 128) {
                int rg = tb + tid;
                y2s[(buf ^ 1) * 128 + tid] = (rg < M_ROWS) ? g_y2[rg] : FLT_MAX;
            }
            asm volatile("cp.async.commit_group;" ::: "memory");
            asm volatile("cp.async.wait_group 1;" ::: "memory");
        } else {
            asm volatile("cp.async.wait_group 0;" ::: "memory");
        }
        __syncthreads();   // B[buf] visible

        // ---- GEMM: warp tile 32(q) x 64(r), K=128, A from registers
        float acc[2][8][4];
        #pragma unroll
        for (int mt = 0; mt < 2; mt++)
            #pragma unroll
            for (int nt = 0; nt < 8; nt++)
                #pragma unroll
                for (int e = 0; e < 4; e++) acc[mt][nt][e] = 0.f;

        const uint32_t Bbase = Bb + (wn * 64) * AB_STRIDE;
        #pragma unroll
        for (int ks = 0; ks < 8; ks++) {
            uint32_t b[8][2];
            #pragma unroll
            for (int nt2 = 0; nt2 < 4; nt2++) {
                uint32_t r0, r1, r2, r3;
                ldsm_x4(r0, r1, r2, r3,
                        Bbase + (nt2 * 16 + brow) * AB_STRIDE + ks * 32 + bcol);
                b[nt2 * 2][0] = r0; b[nt2 * 2][1] = r1;
                b[nt2 * 2 + 1][0] = r2; b[nt2 * 2 + 1][1] = r3;
            }
            #pragma unroll
            for (int mt = 0; mt < 2; mt++)
                #pragma unroll
                for (int nt = 0; nt < 8; nt++)
                    mma16816(acc[mt][nt][0], acc[mt][nt][1], acc[mt][nt][2], acc[mt][nt][3],
                             afr[ks][mt][0], afr[ks][mt][1], afr[ks][mt][2], afr[ks][mt][3],
                             b[nt][0], b[nt][1]);
        }

        // ---- STS D bf16, rotated slot = (4nt+c+3row)&31 -> conflict-free
        const float* y2t = y2s + buf * 128;
        const uint32_t Db = sb + SM_D;
        const int c = lane & 3;
        #pragma unroll
        for (int mt = 0; mt < 2; mt++) {
            int row0 = wm * 32 + mt * 16 + (lane >> 2);
            #pragma unroll
            for (int nt = 0; nt < 8; nt++) {
                int col = wn * 64 + nt * 8 + 2 * c;
                float2 y2p = *reinterpret_cast<const float2*>(y2t + col);
                uint32_t d0 = pack_bf16x2(acc[mt][nt][0] + y2p.x, acc[mt][nt][1] + y2p.y);
                uint32_t d1 = pack_bf16x2(acc[mt][nt][2] + y2p.x, acc[mt][nt][3] + y2p.y);
                int s0 = (4 * nt + c + 3 * row0) & 31;
                int s1 = (4 * nt + c + 3 * (row0 + 8)) & 31;
                uint32_t a0 = Db + row0 * D_STRIDE_B + (wn * 32 + s0) * 4;
                uint32_t a1 = Db + (row0 + 8) * D_STRIDE_B + (wn * 32 + s1) * 4;
                asm volatile("st.shared.b32 [%0], %1;" :: "r"(a0), "r"(d0) : "memory");
                asm volatile("st.shared.b32 [%0], %1;" :: "r"(a1), "r"(d1) : "memory");
            }
        }
        __syncthreads();   // D ready

        // ---- scan: 64 values for (sq, sh); gated 8-at-a-time via hmin2
        const int idx_base = row_beg + t * TILE_R + sh * 64;
        const uint32_t rowb = sb + SM_D + sq * D_STRIDE_B + sh * 128;
        const int rot = (-3 * sq) & 31;     // cp = (j + rot) & 31
        #pragma unroll
        for (int j8 = 0; j8 < 32; j8 += 4) {
            uint32_t w[4];
            #pragma unroll
            for (int i = 0; i < 4; i++)
                asm volatile("ld.shared.b32 %0, [%1];"
                             : "=r"(w[i]) : "r"(rowb + (j8 + i) * 4));
            __nv_bfloat162 b0 = *reinterpret_cast<__nv_bfloat162*>(&w[0]);
            __nv_bfloat162 b1 = *reinterpret_cast<__nv_bfloat162*>(&w[1]);
            __nv_bfloat162 b2 = *reinterpret_cast<__nv_bfloat162*>(&w[2]);
            __nv_bfloat162 b3 = *reinterpret_cast<__nv_bfloat162*>(&w[3]);
            __nv_bfloat162 m = __hmin2(__hmin2(b0, b1), __hmin2(b2, b3));
            float mn = fminf(__low2float(m), __high2float(m));
            if (mn < tv[7]) {
                #pragma unroll
                for (int i = 0; i < 4; i++) {
                    float2 f = __bfloat1622float2(*reinterpret_cast<__nv_bfloat162*>(&w[i]));
                    float vv[2] = {f.x, f.y};
                    #pragma unroll
                    for (int e = 0; e < 2; e++) {
                        float val = vv[e];
                        if (val < tv[7]) {
                            int cp = (j8 + i + rot) & 31;
                            tv[7] = val; tix[7] = idx_base + 2 * cp + e;
                            #pragma unroll
                            for (int k = 7; k > 0; k--) {
                                if (tv[k] < tv[k - 1]) {
                                    float tf = tv[k - 1]; tv[k - 1] = tv[k]; tv[k] = tf;
                                    int   ti = tix[k - 1]; tix[k - 1] = tix[k]; tix[k] = ti;
                                }
                            }
                        }
                    }
                }
            }
        }
    }

    // Write candidates.
    #pragma unroll
    for (int k = 0; k < 8; k++) {
        g_cand_val[slice][qblock + sq][sh * 8 + k] = tv[k];
        g_cand_idx[slice][qblock + sq][sh * 8 + k] = tix[k];
    }
}

// ---------------------------------------------------------------------------
// Refine: per query (one warp): approx-top-16 of 144 candidates -> exact fp32
// distances -> top-5 -> sqrt, normalize, mean.
__global__ void __launch_bounds__(256)
refine_kernel(const float* __restrict__ F, const float* __restrict__ B,
              const float* __restrict__ minv, const float* __restrict__ maxv,
              float* __restrict__ out) {
    __shared__ float sv[8][NSLICES * TPQ];
    __shared__ int   si[8][NSLICES * TPQ];
    __shared__ int   sel[8][RSEL];
    __shared__ float ex[8][RSEL];

    const int w    = threadIdx.x >> 5;
    const int lane = threadIdx.x & 31;
    const int q    = blockIdx.x * 8 + w;
    const int NC   = NSLICES * TPQ;   // 144

    for (int i = lane; i < NC; i += 32) {
        sv[w][i] = g_cand_val[i / TPQ][q][i % TPQ];
        si[w][i] = g_cand_idx[i / TPQ][q][i % TPQ];
    }
    __syncwarp();

    float4 xv = reinterpret_cast<const float4*>(F + (size_t)q * DIMS)[lane];
    float x2 = xv.x*xv.x + xv.y*xv.y + xv.z*xv.z + xv.w*xv.w;
    #pragma unroll
    for (int o = 16; o; o >>= 1) x2 += __shfl_xor_sync(0xffffffffu, x2, o);

    for (int i = lane; i < NC; i += 32) {
        float v = sv[w][i];
        int r = 0;
        for (int j = 0; j < NC; j++) {
            float u = sv[w][j];
            r += (u < v) || (u == v && j < i);
        }
        if (r < RSEL) sel[w][r] = si[w][i];
    }
    __syncwarp();

    for (int cc = 0; cc < RSEL; cc++) {
        int id = sel[w][cc];
        float d2 = FLT_MAX;
        if (id >= 0) {
            float4 yv = reinterpret_cast<const float4*>(B + (size_t)id * DIMS)[lane];
            float p = yv.x*yv.x + yv.y*yv.y + yv.z*yv.z + yv.w*yv.w
                    - 2.0f * (xv.x*yv.x + xv.y*yv.y + xv.z*yv.z + xv.w*yv.w);
            #pragma unroll
            for (int o = 16; o; o >>= 1) p += __shfl_xor_sync(0xffffffffu, p, o);
            d2 = x2 + p;
        }
        if (lane == 0) ex[w][cc] = d2;
    }
    __syncwarp();

    if (lane == 0) {
        float best[KNN];
        #pragma unroll
        for (int k = 0; k < KNN; k++) best[k] = FLT_MAX;
        #pragma unroll
        for (int cc = 0; cc < RSEL; cc++) {
            float v = ex[w][cc];
            if (v < best[KNN - 1]) {
                best[KNN - 1] = v;
                #pragma unroll
                for (int k = KNN - 1; k > 0; k--) {
                    if (best[k] < best[k - 1]) {
                        float tf = best[k - 1]; best[k - 1] = best[k]; best[k] = tf;
                    }
                }
            }
        }
        float mn = *minv, mx = *maxv;
        float inv = 1.f / (mx - mn);
        float sum = 0.f;
        #pragma unroll
        for (int k = 0; k < KNN; k++)
            sum += (sqrtf(fmaxf(best[k], 0.f)) - mn) * inv;
        out[q] = sum * (1.0f / KNN);
    }
}

// ---------------------------------------------------------------------------
extern "C" void kernel_launch(void* const* d_in, const int* in_sizes, int n_in,
                              void* d_out, int out_size) {
    const float* F    = (const float*)d_in[0];
    const float* B    = (const float*)d_in[1];
    const float* minv = (const float*)d_in[2];
    const float* maxv = (const float*)d_in[3];
    float* out = (float*)d_out;

    static bool attr_done = false;
    if (!attr_done) {
        cudaFuncSetAttribute(knn_mma_kernel,
                             cudaFuncAttributeMaxDynamicSharedMemorySize, SMEM_TOTAL);
        attr_done = true;
    }

    int conv_blocks = ((N_Q + M_ROWS) * 32 + 255) / 256;
    convert_kernel<<<conv_blocks, 256>>>(F, B);

    dim3 grid(N_Q / QT, NSLICES);
    knn_mma_kernel<<<grid, TPB, SMEM_TOTAL>>>();

    refine_kernel<<<N_Q / 8, 256>>>(F, B, minv, maxv, out);
}

// round 6
// speedup vs baseline: 5.6931x; 1.9588x over previous
#include <cuda_runtime.h>
#include <cuda_bf16.h>
#include <cstdint>
#include <cfloat>

#define N_Q     2048
#define M_ROWS  100000
#define DIMS    128
#define KNN     5

#define NSLICES   9
#define TILE_R    128
#define NTILES    87
#define SLICE_LEN (NTILES * TILE_R)   // 11136; 9*11136 >= 100000
#define QT        64                   // queries per CTA
#define TPB       256                  // 8 warps

#define KEEP      6                    // kept per (query, quarter, slice)
#define TPQ_TOT   24                   // 4 quarters * KEEP
#define RSEL      16                   // exact-refined candidates per query

// ---- device scratch ----
__device__ __nv_bfloat16 g_hiF2[N_Q * DIMS];     // bf16(-2*F)
__device__ __nv_bfloat16 g_hiB [M_ROWS * DIMS];  // bf16(B)
__device__ float g_y2[M_ROWS];
__device__ float g_cand_val[NSLICES][N_Q][TPQ_TOT];
__device__ int   g_cand_idx[NSLICES][N_Q][TPQ_TOT];

// ---- smem layout (bytes) ----
#define AB_STRIDE 272                  // A/B row stride: conflict-free LDSM
#define SM_A    0                      // 64*272  = 17408
#define SM_B0   17408                  // 128*272 = 34816
#define SM_B1   52224
#define SM_D    87040                  // bf16 D: 64 rows * 260B = 16640
#define D_STRIDE_B 260                 // 65 words (odd)
#define SM_Y2   103680                 // float[2][128]
#define SMEM_TOTAL 104704

// ---------------------------------------------------------------------------
__device__ __forceinline__ uint32_t s2u(const void* p) {
    uint32_t a;
    asm("{ .reg .u64 t; cvta.to.shared.u64 t, %1; cvt.u32.u64 %0, t; }" : "=r"(a) : "l"(p));
    return a;
}
__device__ __forceinline__ void cp16(uint32_t dst, const void* src) {
    asm volatile("cp.async.cg.shared.global [%0], [%1], 16;" :: "r"(dst), "l"(src) : "memory");
}
__device__ __forceinline__ void ldsm_x4(uint32_t& r0, uint32_t& r1, uint32_t& r2, uint32_t& r3,
                                        uint32_t addr) {
    asm volatile("ldmatrix.sync.aligned.m8n8.x4.shared.b16 {%0,%1,%2,%3}, [%4];"
                 : "=r"(r0), "=r"(r1), "=r"(r2), "=r"(r3) : "r"(addr));
}
__device__ __forceinline__ void mma16816(float& d0, float& d1, float& d2, float& d3,
                                         uint32_t a0, uint32_t a1, uint32_t a2, uint32_t a3,
                                         uint32_t b0, uint32_t b1) {
    asm volatile("mma.sync.aligned.m16n8k16.row.col.f32.bf16.bf16.f32 "
                 "{%0,%1,%2,%3}, {%4,%5,%6,%7}, {%8,%9}, {%0,%1,%2,%3};"
                 : "+f"(d0), "+f"(d1), "+f"(d2), "+f"(d3)
                 : "r"(a0), "r"(a1), "r"(a2), "r"(a3), "r"(b0), "r"(b1));
}
__device__ __forceinline__ uint32_t pack_bf16x2(float lo, float hi) {
    uint32_t d;
    asm("cvt.rn.bf16x2.f32 %0, %1, %2;" : "=r"(d) : "f"(hi), "f"(lo));
    return d;
}

// ---------------------------------------------------------------------------
// Convert: bf16(B) rows, bf16(-2*F) rows, y2 norms. One warp per row.
__global__ void convert_kernel(const float* __restrict__ F, const float* __restrict__ B) {
    int gw   = (blockIdx.x * blockDim.x + threadIdx.x) >> 5;
    int lane = threadIdx.x & 31;
    if (gw >= N_Q + M_ROWS) return;
    bool isF = gw < N_Q;
    int row  = isF ? gw : gw - N_Q;
    const float* src = (isF ? F : B) + (size_t)row * DIMS;
    float4 v = reinterpret_cast<const float4*>(src)[lane];
    if (!isF) {
        float s = v.x*v.x + v.y*v.y + v.z*v.z + v.w*v.w;
        #pragma unroll
        for (int o = 16; o; o >>= 1) s += __shfl_xor_sync(0xffffffffu, s, o);
        if (lane == 0) g_y2[row] = s;
    }
    float sc = isF ? -2.0f : 1.0f;
    __nv_bfloat162 p0{__float2bfloat16_rn(sc * v.x), __float2bfloat16_rn(sc * v.y)};
    __nv_bfloat162 p1{__float2bfloat16_rn(sc * v.z), __float2bfloat16_rn(sc * v.w)};
    __nv_bfloat162* hp = reinterpret_cast<__nv_bfloat162*>(isF ? g_hiF2 : g_hiB);
    hp[(size_t)row * 64 + 2 * lane]     = p0;
    hp[(size_t)row * 64 + 2 * lane + 1] = p1;
}

// ---------------------------------------------------------------------------
// Main: mma.sync GEMM + bf16 D + scan. QT=64 -> 2 CTAs/SM for phase overlap.
__global__ void __launch_bounds__(TPB, 2)
knn_mma_kernel() {
    extern __shared__ char smem[];
    const uint32_t sb = s2u(smem);
    float* y2s = reinterpret_cast<float*>(smem + SM_Y2);

    const int tid  = threadIdx.x;
    const int wid  = tid >> 5;
    const int lane = tid & 31;
    const int wm   = wid & 3;        // 4 m-chunks of 16 rows
    const int wn   = wid >> 2;       // 2 n-chunks of 64 cols
    const int qblock  = blockIdx.x * QT;
    const int slice   = blockIdx.y;
    const int row_beg = slice * SLICE_LEN;

    // Stage A (64 queries): 1024 16B chunks, 4 per thread.
    #pragma unroll
    for (int i = 0; i < 4; i++) {
        int chunk = tid + TPB * i;
        int r = chunk >> 4, cc = chunk & 15;
        uint4 v = *reinterpret_cast<const uint4*>(
            reinterpret_cast<const char*>(g_hiF2) + ((size_t)(qblock + r) * 256 + cc * 16));
        *reinterpret_cast<uint4*>(smem + SM_A + r * AB_STRIDE + cc * 16) = v;
    }
    // Prefetch B tile 0 into buffer 0.
    {
        #pragma unroll
        for (int i = 0; i < 8; i++) {
            int chunk = tid + TPB * i;
            int r = chunk >> 4, cc = chunk & 15;
            int rg = row_beg + r;
            int rc = rg < M_ROWS ? rg : M_ROWS - 1;
            cp16(sb + SM_B0 + r * AB_STRIDE + cc * 16,
                 reinterpret_cast<const char*>(g_hiB) + ((size_t)rc * 256 + cc * 16));
        }
        if (tid < 128) {
            int rg = row_beg + tid;
            y2s[tid] = (rg < M_ROWS) ? g_y2[rg] : FLT_MAX;
        }
        asm volatile("cp.async.commit_group;" ::: "memory");
    }
    __syncthreads();

    // Hoist A fragments (one 16-row m-tile -> 32 regs), loop-invariant.
    const int arow = lane & 15;
    const int acol = (lane >> 4) * 16;
    const int brow = (lane & 7) + (lane >> 4) * 8;
    const int bcol = ((lane >> 3) & 1) * 16;
    const uint32_t Abase = sb + SM_A + (wm * 16) * AB_STRIDE;
    uint32_t afr[8][4];
    #pragma unroll
    for (int ks = 0; ks < 8; ks++)
        ldsm_x4(afr[ks][0], afr[ks][1], afr[ks][2], afr[ks][3],
                Abase + arow * AB_STRIDE + ks * 32 + acol);

    // Scan state: thread owns (query sq, quarter sh). Top-KEEP ascending.
    const int sq = tid & 63;
    const int sh = tid >> 6;             // 0..3
    const int h  = sh >> 1;              // which 64-col half
    const int qh = sh & 1;               // which 16-word quarter of that half
    const int rot = (32 - ((3 * sq) & 31)) & 31;
    float tv[KEEP]; int tix[KEEP];
    #pragma unroll
    for (int k = 0; k < KEEP; k++) { tv[k] = FLT_MAX; tix[k] = -1; }

    for (int t = 0; t < NTILES; t++) {
        const int buf = t & 1;
        const uint32_t Bb = sb + (buf ? SM_B1 : SM_B0);

        __syncthreads();   // prev scan done; B[buf^1] consumed

        if (t + 1 < NTILES) {
            int tb = row_beg + (t + 1) * TILE_R;
            uint32_t Bn = sb + (buf ? SM_B0 : SM_B1);
            #pragma unroll
            for (int i = 0; i < 8; i++) {
                int chunk = tid + TPB * i;
                int r = chunk >> 4, cc = chunk & 15;
                int rg = tb + r;
                int rc = rg < M_ROWS ? rg : M_ROWS - 1;
                cp16(Bn + r * AB_STRIDE + cc * 16,
                     reinterpret_cast<const char*>(g_hiB) + ((size_t)rc * 256 + cc * 16));
            }
            if (tid < 128) {
                int rg = tb + tid;
                y2s[(buf ^ 1) * 128 + tid] = (rg < M_ROWS) ? g_y2[rg] : FLT_MAX;
            }
            asm volatile("cp.async.commit_group;" ::: "memory");
            asm volatile("cp.async.wait_group 1;" ::: "memory");
        } else {
            asm volatile("cp.async.wait_group 0;" ::: "memory");
        }
        __syncthreads();   // B[buf] visible

        // ---- GEMM: warp tile 16(q) x 64(r), K=128, A from registers
        float acc[8][4];
        #pragma unroll
        for (int nt = 0; nt < 8; nt++)
            #pragma unroll
            for (int e = 0; e < 4; e++) acc[nt][e] = 0.f;

        const uint32_t Bbase = Bb + (wn * 64) * AB_STRIDE;
        #pragma unroll
        for (int ks = 0; ks < 8; ks++) {
            uint32_t b[8][2];
            #pragma unroll
            for (int nt2 = 0; nt2 < 4; nt2++) {
                uint32_t r0, r1, r2, r3;
                ldsm_x4(r0, r1, r2, r3,
                        Bbase + (nt2 * 16 + brow) * AB_STRIDE + ks * 32 + bcol);
                b[nt2 * 2][0] = r0; b[nt2 * 2][1] = r1;
                b[nt2 * 2 + 1][0] = r2; b[nt2 * 2 + 1][1] = r3;
            }
            #pragma unroll
            for (int nt = 0; nt < 8; nt++)
                mma16816(acc[nt][0], acc[nt][1], acc[nt][2], acc[nt][3],
                         afr[ks][0], afr[ks][1], afr[ks][2], afr[ks][3],
                         b[nt][0], b[nt][1]);
        }

        // ---- STS D bf16, slot rotation s=(p+3*row)&31 within 32-word half.
        // bank = (65*row + wn*32 + s) mod 32 = lane + const -> conflict-free.
        const float* y2t = y2s + buf * 128;
        const uint32_t Db = sb + SM_D;
        const int c = lane & 3;
        const int row0 = wm * 16 + (lane >> 2);
        #pragma unroll
        for (int nt = 0; nt < 8; nt++) {
            int col = wn * 64 + nt * 8 + 2 * c;
            float2 y2p = *reinterpret_cast<const float2*>(y2t + col);
            uint32_t d0 = pack_bf16x2(acc[nt][0] + y2p.x, acc[nt][1] + y2p.y);
            uint32_t d1 = pack_bf16x2(acc[nt][2] + y2p.x, acc[nt][3] + y2p.y);
            int p  = nt * 4 + c;
            int s0 = (p + 3 * row0) & 31;
            int s1 = (p + 3 * (row0 + 8)) & 31;
            uint32_t a0 = Db + row0 * D_STRIDE_B + (wn * 32 + s0) * 4;
            uint32_t a1 = Db + (row0 + 8) * D_STRIDE_B + (wn * 32 + s1) * 4;
            asm volatile("st.shared.b32 [%0], %1;" :: "r"(a0), "r"(d0) : "memory");
            asm volatile("st.shared.b32 [%0], %1;" :: "r"(a1), "r"(d1) : "memory");
        }
        __syncthreads();   // D ready

        // ---- scan: 32 values (16 words) for (sq, quarter sh)
        const int idx_base = row_beg + t * TILE_R + h * 64;
        const uint32_t rowb = sb + SM_D + sq * D_STRIDE_B + h * 128 + qh * 64;
        #pragma unroll
        for (int j = 0; j < 16; j++) {
            uint32_t w;
            asm volatile("ld.shared.b32 %0, [%1];" : "=r"(w) : "r"(rowb + j * 4));
            float2 f = __bfloat1622float2(*reinterpret_cast<__nv_bfloat162*>(&w));
            float vv[2] = {f.x, f.y};
            #pragma unroll
            for (int e = 0; e < 2; e++) {
                float val = vv[e];
                if (val < tv[KEEP - 1]) {
                    int p = ((qh * 16 + j) + rot) & 31;
                    tv[KEEP - 1] = val;
                    tix[KEEP - 1] = idx_base + 2 * p + e;
                    #pragma unroll
                    for (int k = KEEP - 1; k > 0; k--) {
                        if (tv[k] < tv[k - 1]) {
                            float tf = tv[k - 1]; tv[k - 1] = tv[k]; tv[k] = tf;
                            int   ti = tix[k - 1]; tix[k - 1] = tix[k]; tix[k] = ti;
                        }
                    }
                }
            }
        }
    }

    // Write candidates.
    #pragma unroll
    for (int k = 0; k < KEEP; k++) {
        g_cand_val[slice][qblock + sq][sh * KEEP + k] = tv[k];
        g_cand_idx[slice][qblock + sq][sh * KEEP + k] = tix[k];
    }
}

// ---------------------------------------------------------------------------
// Refine: per query (one warp): approx-top-16 of 216 candidates -> exact fp32
// distances -> top-5 -> sqrt, normalize, mean.
__global__ void __launch_bounds__(256)
refine_kernel(const float* __restrict__ F, const float* __restrict__ B,
              const float* __restrict__ minv, const float* __restrict__ maxv,
              float* __restrict__ out) {
    __shared__ float sv[8][NSLICES * TPQ_TOT];
    __shared__ int   si[8][NSLICES * TPQ_TOT];
    __shared__ int   sel[8][RSEL];
    __shared__ float ex[8][RSEL];

    const int w    = threadIdx.x >> 5;
    const int lane = threadIdx.x & 31;
    const int q    = blockIdx.x * 8 + w;
    const int NC   = NSLICES * TPQ_TOT;   // 216

    for (int i = lane; i < NC; i += 32) {
        sv[w][i] = g_cand_val[i / TPQ_TOT][q][i % TPQ_TOT];
        si[w][i] = g_cand_idx[i / TPQ_TOT][q][i % TPQ_TOT];
    }
    __syncwarp();

    float4 xv = reinterpret_cast<const float4*>(F + (size_t)q * DIMS)[lane];
    float x2 = xv.x*xv.x + xv.y*xv.y + xv.z*xv.z + xv.w*xv.w;
    #pragma unroll
    for (int o = 16; o; o >>= 1) x2 += __shfl_xor_sync(0xffffffffu, x2, o);

    for (int i = lane; i < NC; i += 32) {
        float v = sv[w][i];
        int r = 0;
        for (int j = 0; j < NC; j++) {
            float u = sv[w][j];
            r += (u < v) || (u == v && j < i);
        }
        if (r < RSEL) sel[w][r] = si[w][i];
    }
    __syncwarp();

    for (int cc = 0; cc < RSEL; cc++) {
        int id = sel[w][cc];
        float d2 = FLT_MAX;
        if (id >= 0) {
            float4 yv = reinterpret_cast<const float4*>(B + (size_t)id * DIMS)[lane];
            float p = yv.x*yv.x + yv.y*yv.y + yv.z*yv.z + yv.w*yv.w
                    - 2.0f * (xv.x*yv.x + xv.y*yv.y + xv.z*yv.z + xv.w*yv.w);
            #pragma unroll
            for (int o = 16; o; o >>= 1) p += __shfl_xor_sync(0xffffffffu, p, o);
            d2 = x2 + p;
        }
        if (lane == 0) ex[w][cc] = d2;
    }
    __syncwarp();

    if (lane == 0) {
        float best[KNN];
        #pragma unroll
        for (int k = 0; k < KNN; k++) best[k] = FLT_MAX;
        #pragma unroll
        for (int cc = 0; cc < RSEL; cc++) {
            float v = ex[w][cc];
            if (v < best[KNN - 1]) {
                best[KNN - 1] = v;
                #pragma unroll
                for (int k = KNN - 1; k > 0; k--) {
                    if (best[k] < best[k - 1]) {
                        float tf = best[k - 1]; best[k - 1] = best[k]; best[k] = tf;
                    }
                }
            }
        }
        float mn = *minv, mx = *maxv;
        float inv = 1.f / (mx - mn);
        float sum = 0.f;
        #pragma unroll
        for (int k = 0; k < KNN; k++)
            sum += (sqrtf(fmaxf(best[k], 0.f)) - mn) * inv;
        out[q] = sum * (1.0f / KNN);
    }
}

// ---------------------------------------------------------------------------
extern "C" void kernel_launch(void* const* d_in, const int* in_sizes, int n_in,
                              void* d_out, int out_size) {
    const float* F    = (const float*)d_in[0];
    const float* B    = (const float*)d_in[1];
    const float* minv = (const float*)d_in[2];
    const float* maxv = (const float*)d_in[3];
    float* out = (float*)d_out;

    static bool attr_done = false;
    if (!attr_done) {
        cudaFuncSetAttribute(knn_mma_kernel,
                             cudaFuncAttributeMaxDynamicSharedMemorySize, SMEM_TOTAL);
        attr_done = true;
    }

    int conv_blocks = ((N_Q + M_ROWS) * 32 + 255) / 256;
    convert_kernel<<<conv_blocks, 256>>>(F, B);

    dim3 grid(N_Q / QT, NSLICES);
    knn_mma_kernel<<<grid, TPB, SMEM_TOTAL>>>();

    refine_kernel<<<N_Q / 8, 256>>>(F, B, minv, maxv, out);
}

// round 7
// speedup vs baseline: 6.4357x; 1.1304x over previous
#include <cuda_runtime.h>
#include <cuda_bf16.h>
#include <cstdint>
#include <cfloat>

#define N_Q     2048
#define M_ROWS  100000
#define DIMS    128
#define KNN     5

#define NSLICES   9
#define TILE_R    128
#define NTILES    87
#define SLICE_LEN (NTILES * TILE_R)   // 11136; 9*11136 >= 100000
#define QT        64                   // queries per CTA
#define TPB       256                  // 8 warps

#define KEEP      4                    // kept per (query, 16-col subset, slice)
#define TPQ_TOT   32                   // 8 subsets * KEEP
#define RSEL      16                   // exact-refined candidates per query

// ---- device scratch ----
__device__ __nv_bfloat16 g_hiF2[N_Q * DIMS];     // bf16(-2*F)
__device__ __nv_bfloat16 g_hiB [M_ROWS * DIMS];  // bf16(B)
__device__ float g_y2[M_ROWS];
__device__ float g_cand_val[NSLICES][N_Q][TPQ_TOT];
__device__ int   g_cand_idx[NSLICES][N_Q][TPQ_TOT];

// ---- smem layout (bytes) ----
#define AB_STRIDE 272                  // A/B row stride: conflict-free LDSM
#define SM_A    0                      // 64*272  = 17408
#define SM_B0   17408                  // 128*272 = 34816
#define SM_B1   52224
#define SM_Y2   87040                  // float[2][128]
#define SMEM_TOTAL 88064

// ---------------------------------------------------------------------------
__device__ __forceinline__ uint32_t s2u(const void* p) {
    uint32_t a;
    asm("{ .reg .u64 t; cvta.to.shared.u64 t, %1; cvt.u32.u64 %0, t; }" : "=r"(a) : "l"(p));
    return a;
}
__device__ __forceinline__ void cp16(uint32_t dst, const void* src) {
    asm volatile("cp.async.cg.shared.global [%0], [%1], 16;" :: "r"(dst), "l"(src) : "memory");
}
__device__ __forceinline__ void ldsm_x4(uint32_t& r0, uint32_t& r1, uint32_t& r2, uint32_t& r3,
                                        uint32_t addr) {
    asm volatile("ldmatrix.sync.aligned.m8n8.x4.shared.b16 {%0,%1,%2,%3}, [%4];"
                 : "=r"(r0), "=r"(r1), "=r"(r2), "=r"(r3) : "r"(addr));
}
__device__ __forceinline__ void mma16816(float& d0, float& d1, float& d2, float& d3,
                                         uint32_t a0, uint32_t a1, uint32_t a2, uint32_t a3,
                                         uint32_t b0, uint32_t b1) {
    asm volatile("mma.sync.aligned.m16n8k16.row.col.f32.bf16.bf16.f32 "
                 "{%0,%1,%2,%3}, {%4,%5,%6,%7}, {%8,%9}, {%0,%1,%2,%3};"
                 : "+f"(d0), "+f"(d1), "+f"(d2), "+f"(d3)
                 : "r"(a0), "r"(a1), "r"(a2), "r"(a3), "r"(b0), "r"(b1));
}

// ---------------------------------------------------------------------------
// Convert: bf16(B) rows, bf16(-2*F) rows, y2 norms. One warp per row.
__global__ void convert_kernel(const float* __restrict__ F, const float* __restrict__ B) {
    int gw   = (blockIdx.x * blockDim.x + threadIdx.x) >> 5;
    int lane = threadIdx.x & 31;
    if (gw >= N_Q + M_ROWS) return;
    bool isF = gw < N_Q;
    int row  = isF ? gw : gw - N_Q;
    const float* src = (isF ? F : B) + (size_t)row * DIMS;
    float4 v = reinterpret_cast<const float4*>(src)[lane];
    if (!isF) {
        float s = v.x*v.x + v.y*v.y + v.z*v.z + v.w*v.w;
        #pragma unroll
        for (int o = 16; o; o >>= 1) s += __shfl_xor_sync(0xffffffffu, s, o);
        if (lane == 0) g_y2[row] = s;
    }
    float sc = isF ? -2.0f : 1.0f;
    __nv_bfloat162 p0{__float2bfloat16_rn(sc * v.x), __float2bfloat16_rn(sc * v.y)};
    __nv_bfloat162 p1{__float2bfloat16_rn(sc * v.z), __float2bfloat16_rn(sc * v.w)};
    __nv_bfloat162* hp = reinterpret_cast<__nv_bfloat162*>(isF ? g_hiF2 : g_hiB);
    hp[(size_t)row * 64 + 2 * lane]     = p0;
    hp[(size_t)row * 64 + 2 * lane + 1] = p1;
}

// ---------------------------------------------------------------------------
// Main: mma.sync GEMM + in-register top-4 selection (no D buffer).
// Thread owns query rows (wm*16 + lane/4) and (+8), cols [wn*64 .. +64) at
// positions nt*8 + 2*(lane&3) + e.
__global__ void __launch_bounds__(TPB, 2)
knn_mma_kernel() {
    extern __shared__ char smem[];
    const uint32_t sb = s2u(smem);
    float* y2s = reinterpret_cast<float*>(smem + SM_Y2);

    const int tid  = threadIdx.x;
    const int wid  = tid >> 5;
    const int lane = tid & 31;
    const int wm   = wid & 3;        // 4 m-chunks of 16 rows
    const int wn   = wid >> 2;       // 2 n-chunks of 64 cols
    const int qblock  = blockIdx.x * QT;
    const int slice   = blockIdx.y;
    const int row_beg = slice * SLICE_LEN;

    // Stage A (64 queries): 1024 16B chunks, 4 per thread.
    #pragma unroll
    for (int i = 0; i < 4; i++) {
        int chunk = tid + TPB * i;
        int r = chunk >> 4, cc = chunk & 15;
        uint4 v = *reinterpret_cast<const uint4*>(
            reinterpret_cast<const char*>(g_hiF2) + ((size_t)(qblock + r) * 256 + cc * 16));
        *reinterpret_cast<uint4*>(smem + SM_A + r * AB_STRIDE + cc * 16) = v;
    }
    // Prefetch B tile 0 into buffer 0.
    {
        #pragma unroll
        for (int i = 0; i < 8; i++) {
            int chunk = tid + TPB * i;
            int r = chunk >> 4, cc = chunk & 15;
            int rg = row_beg + r;
            int rc = rg < M_ROWS ? rg : M_ROWS - 1;
            cp16(sb + SM_B0 + r * AB_STRIDE + cc * 16,
                 reinterpret_cast<const char*>(g_hiB) + ((size_t)rc * 256 + cc * 16));
        }
        if (tid < 128) {
            int rg = row_beg + tid;
            y2s[tid] = (rg < M_ROWS) ? g_y2[rg] : FLT_MAX;
        }
        asm volatile("cp.async.commit_group;" ::: "memory");
    }
    __syncthreads();

    // Hoist A fragments (16-row m-tile -> 32 regs), loop-invariant.
    const int arow = lane & 15;
    const int acol = (lane >> 4) * 16;
    const int brow = (lane & 7) + (lane >> 4) * 8;
    const int bcol = ((lane >> 3) & 1) * 16;
    const uint32_t Abase = sb + SM_A + (wm * 16) * AB_STRIDE;
    uint32_t afr[8][4];
    #pragma unroll
    for (int ks = 0; ks < 8; ks++)
        ldsm_x4(afr[ks][0], afr[ks][1], afr[ks][2], afr[ks][3],
                Abase + arow * AB_STRIDE + ks * 32 + acol);

    // Selection state: two owned query-rows, top-KEEP (ascending) each.
    float tv0[KEEP], tv1[KEEP]; int ti0[KEEP], ti1[KEEP];
    #pragma unroll
    for (int k = 0; k < KEEP; k++) {
        tv0[k] = FLT_MAX; ti0[k] = -1;
        tv1[k] = FLT_MAX; ti1[k] = -1;
    }

    for (int t = 0; t < NTILES; t++) {
        const int buf = t & 1;
        const uint32_t Bb = sb + (buf ? SM_B1 : SM_B0);

        __syncthreads();   // prev GEMM+select done; B[buf^1], y2s[buf^1] free

        if (t + 1 < NTILES) {
            int tb = row_beg + (t + 1) * TILE_R;
            uint32_t Bn = sb + (buf ? SM_B0 : SM_B1);
            #pragma unroll
            for (int i = 0; i < 8; i++) {
                int chunk = tid + TPB * i;
                int r = chunk >> 4, cc = chunk & 15;
                int rg = tb + r;
                int rc = rg < M_ROWS ? rg : M_ROWS - 1;
                cp16(Bn + r * AB_STRIDE + cc * 16,
                     reinterpret_cast<const char*>(g_hiB) + ((size_t)rc * 256 + cc * 16));
            }
            if (tid < 128) {
                int rg = tb + tid;
                y2s[(buf ^ 1) * 128 + tid] = (rg < M_ROWS) ? g_y2[rg] : FLT_MAX;
            }
            asm volatile("cp.async.commit_group;" ::: "memory");
            asm volatile("cp.async.wait_group 1;" ::: "memory");
        } else {
            asm volatile("cp.async.wait_group 0;" ::: "memory");
        }
        __syncthreads();   // B[buf] visible

        // ---- GEMM: warp tile 16(q) x 64(r), K=128, A from registers
        float acc[8][4];
        #pragma unroll
        for (int nt = 0; nt < 8; nt++)
            #pragma unroll
            for (int e = 0; e < 4; e++) acc[nt][e] = 0.f;

        const uint32_t Bbase = Bb + (wn * 64) * AB_STRIDE;
        #pragma unroll
        for (int ks = 0; ks < 8; ks++) {
            uint32_t b[8][2];
            #pragma unroll
            for (int nt2 = 0; nt2 < 4; nt2++) {
                uint32_t r0, r1, r2, r3;
                ldsm_x4(r0, r1, r2, r3,
                        Bbase + (nt2 * 16 + brow) * AB_STRIDE + ks * 32 + bcol);
                b[nt2 * 2][0] = r0; b[nt2 * 2][1] = r1;
                b[nt2 * 2 + 1][0] = r2; b[nt2 * 2 + 1][1] = r3;
            }
            #pragma unroll
            for (int nt = 0; nt < 8; nt++)
                mma16816(acc[nt][0], acc[nt][1], acc[nt][2], acc[nt][3],
                         afr[ks][0], afr[ks][1], afr[ks][2], afr[ks][3],
                         b[nt][0], b[nt][1]);
        }

        // ---- in-register selection: d2 = acc + y2[col]; update top-KEEP lists
        const float* y2t = y2s + buf * 128;
        const int cbase = wn * 64 + 2 * (lane & 3);
        const int gidx  = row_beg + t * TILE_R + cbase;
        #pragma unroll
        for (int nt = 0; nt < 8; nt++) {
            int col = cbase + nt * 8;
            float2 y2p = *reinterpret_cast<const float2*>(y2t + col);
            float v00 = acc[nt][0] + y2p.x, v01 = acc[nt][1] + y2p.y;
            float v10 = acc[nt][2] + y2p.x, v11 = acc[nt][3] + y2p.y;
            int ib = gidx + nt * 8;

            #pragma unroll
            for (int e = 0; e < 2; e++) {
                float v = e ? v01 : v00;
                if (v < tv0[KEEP - 1]) {
                    tv0[KEEP - 1] = v; ti0[KEEP - 1] = ib + e;
                    #pragma unroll
                    for (int k = KEEP - 1; k > 0; k--) {
                        if (tv0[k] < tv0[k - 1]) {
                            float tf = tv0[k - 1]; tv0[k - 1] = tv0[k]; tv0[k] = tf;
                            int   ti = ti0[k - 1]; ti0[k - 1] = ti0[k]; ti0[k] = ti;
                        }
                    }
                }
            }
            #pragma unroll
            for (int e = 0; e < 2; e++) {
                float v = e ? v11 : v10;
                if (v < tv1[KEEP - 1]) {
                    tv1[KEEP - 1] = v; ti1[KEEP - 1] = ib + e;
                    #pragma unroll
                    for (int k = KEEP - 1; k > 0; k--) {
                        if (tv1[k] < tv1[k - 1]) {
                            float tf = tv1[k - 1]; tv1[k - 1] = tv1[k]; tv1[k] = tf;
                            int   ti = ti1[k - 1]; ti1[k - 1] = ti1[k]; ti1[k] = ti;
                        }
                    }
                }
            }
        }
    }

    // Write candidates: sub-list id = wn*4 + (lane&3), rows q0 and q0+8.
    const int q0  = qblock + wm * 16 + (lane >> 2);
    const int sub = wn * 4 + (lane & 3);
    #pragma unroll
    for (int k = 0; k < KEEP; k++) {
        g_cand_val[slice][q0][sub * KEEP + k]     = tv0[k];
        g_cand_idx[slice][q0][sub * KEEP + k]     = ti0[k];
        g_cand_val[slice][q0 + 8][sub * KEEP + k] = tv1[k];
        g_cand_idx[slice][q0 + 8][sub * KEEP + k] = ti1[k];
    }
}

// ---------------------------------------------------------------------------
// Refine: per query (one warp): approx-top-16 of 288 candidates -> exact fp32
// distances -> top-5 -> sqrt, normalize, mean.
__global__ void __launch_bounds__(256)
refine_kernel(const float* __restrict__ F, const float* __restrict__ B,
              const float* __restrict__ minv, const float* __restrict__ maxv,
              float* __restrict__ out) {
    __shared__ float sv[8][NSLICES * TPQ_TOT];
    __shared__ int   si[8][NSLICES * TPQ_TOT];
    __shared__ int   sel[8][RSEL];
    __shared__ float ex[8][RSEL];

    const int w    = threadIdx.x >> 5;
    const int lane = threadIdx.x & 31;
    const int q    = blockIdx.x * 8 + w;
    const int NC   = NSLICES * TPQ_TOT;   // 288

    for (int i = lane; i < NC; i += 32) {
        sv[w][i] = g_cand_val[i / TPQ_TOT][q][i % TPQ_TOT];
        si[w][i] = g_cand_idx[i / TPQ_TOT][q][i % TPQ_TOT];
    }
    __syncwarp();

    float4 xv = reinterpret_cast<const float4*>(F + (size_t)q * DIMS)[lane];
    float x2 = xv.x*xv.x + xv.y*xv.y + xv.z*xv.z + xv.w*xv.w;
    #pragma unroll
    for (int o = 16; o; o >>= 1) x2 += __shfl_xor_sync(0xffffffffu, x2, o);

    for (int i = lane; i < NC; i += 32) {
        float v = sv[w][i];
        int r = 0;
        for (int j = 0; j < NC; j++) {
            float u = sv[w][j];
            r += (u < v) || (u == v && j < i);
        }
        if (r < RSEL) sel[w][r] = si[w][i];
    }
    __syncwarp();

    for (int cc = 0; cc < RSEL; cc++) {
        int id = sel[w][cc];
        float d2 = FLT_MAX;
        if (id >= 0) {
            float4 yv = reinterpret_cast<const float4*>(B + (size_t)id * DIMS)[lane];
            float p = yv.x*yv.x + yv.y*yv.y + yv.z*yv.z + yv.w*yv.w
                    - 2.0f * (xv.x*yv.x + xv.y*yv.y + xv.z*yv.z + xv.w*yv.w);
            #pragma unroll
            for (int o = 16; o; o >>= 1) p += __shfl_xor_sync(0xffffffffu, p, o);
            d2 = x2 + p;
        }
        if (lane == 0) ex[w][cc] = d2;
    }
    __syncwarp();

    if (lane == 0) {
        float best[KNN];
        #pragma unroll
        for (int k = 0; k < KNN; k++) best[k] = FLT_MAX;
        #pragma unroll
        for (int cc = 0; cc < RSEL; cc++) {
            float v = ex[w][cc];
            if (v < best[KNN - 1]) {
                best[KNN - 1] = v;
                #pragma unroll
                for (int k = KNN - 1; k > 0; k--) {
                    if (best[k] < best[k - 1]) {
                        float tf = best[k - 1]; best[k - 1] = best[k]; best[k] = tf;
                    }
                }
            }
        }
        float mn = *minv, mx = *maxv;
        float inv = 1.f / (mx - mn);
        float sum = 0.f;
        #pragma unroll
        for (int k = 0; k < KNN; k++)
            sum += (sqrtf(fmaxf(best[k], 0.f)) - mn) * inv;
        out[q] = sum * (1.0f / KNN);
    }
}

// ---------------------------------------------------------------------------
extern "C" void kernel_launch(void* const* d_in, const int* in_sizes, int n_in,
                              void* d_out, int out_size) {
    const float* F    = (const float*)d_in[0];
    const float* B    = (const float*)d_in[1];
    const float* minv = (const float*)d_in[2];
    const float* maxv = (const float*)d_in[3];
    float* out = (float*)d_out;

    static bool attr_done = false;
    if (!attr_done) {
        cudaFuncSetAttribute(knn_mma_kernel,
                             cudaFuncAttributeMaxDynamicSharedMemorySize, SMEM_TOTAL);
        attr_done = true;
    }

    int conv_blocks = ((N_Q + M_ROWS) * 32 + 255) / 256;
    convert_kernel<<<conv_blocks, 256>>>(F, B);

    dim3 grid(N_Q / QT, NSLICES);
    knn_mma_kernel<<<grid, TPB, SMEM_TOTAL>>>();

    refine_kernel<<<N_Q / 8, 256>>>(F, B, minv, maxv, out);
}